// round 15
// baseline (speedup 1.0000x reference)
#include <cuda_runtime.h>
#include <cstdint>

#define B_   64
#define S_   2048
#define RNN_ 1024
#define ATT_ 512
#define CTX_ 1024

#define NCHUNK 32
#define SCHUNK (S_ / NCHUNK)   // 64 rows per fused block
#define NGROUP 8               // pipeline groups of 8 rows
#define NGROUPS_PER_BLK (SCHUNK / NGROUP)  // 8

#define KSPLIT 32
#define KCHUNK (RNN_ / KSPLIT) // 32 = exactly one BK tile per block

// Scratch (no allocations allowed in kernel_launch)
__device__ float g_attn_part[KSPLIT * B_ * ATT_];
__device__ float g_attn_h[B_ * ATT_];
__device__ float g_escores[B_ * S_];        // UNNORMALIZED exp(score), masked -> 0
__device__ float g_bsum[B_ * NCHUNK];       // per-block e-sums (32 per batch row)
__device__ float g_partial[NCHUNK * B_ * CTX_];   // UNNORMALIZED e-weighted partials

// ---------------------------------------------------------------------------
// Kernel 1: split-K GEMM partials.  grid = (8 n-tiles, 32 k-chunks) = 256
// blocks, ONE BK=32 k-tile each (no loop-carried smem dependency).
// ---------------------------------------------------------------------------
#define BM 64
#define BN 64
#define BK 32
__global__ __launch_bounds__(256) void attn_h_kernel(
    const float* __restrict__ h, const float* __restrict__ W) {
    __shared__ float As[BM][BK + 1];
    __shared__ float Bs[BN][BK + 1];
    const int a0 = blockIdx.x * BN;
    const int k0 = blockIdx.y * KCHUNK;
    const int tx = threadIdx.x & 15;
    const int ty = threadIdx.x >> 4;
    float acc[4][4] = {};

    for (int i = threadIdx.x; i < BM * BK; i += 256) {
        int r = i >> 5, c = i & 31;
        As[r][c] = h[r * RNN_ + k0 + c];
    }
    for (int i = threadIdx.x; i < BN * BK; i += 256) {
        int r = i >> 5, c = i & 31;
        Bs[r][c] = W[(a0 + r) * RNN_ + k0 + c];
    }
    __syncthreads();
#pragma unroll
    for (int k = 0; k < BK; k++) {
        float av[4], bv[4];
#pragma unroll
        for (int i = 0; i < 4; i++) av[i] = As[ty * 4 + i][k];
#pragma unroll
        for (int j = 0; j < 4; j++) bv[j] = Bs[tx * 4 + j][k];
#pragma unroll
        for (int i = 0; i < 4; i++)
#pragma unroll
            for (int j = 0; j < 4; j++)
                acc[i][j] = fmaf(av[i], bv[j], acc[i][j]);
    }
    float* part = g_attn_part + (size_t)blockIdx.y * B_ * ATT_;
#pragma unroll
    for (int i = 0; i < 4; i++)
#pragma unroll
        for (int j = 0; j < 4; j++)
            part[(ty * 4 + i) * ATT_ + a0 + tx * 4 + j] = acc[i][j];
}

// ---------------------------------------------------------------------------
// Kernel 1b: reduce split-K partials + bias -> attn_h (fixed order).
// ---------------------------------------------------------------------------
__global__ __launch_bounds__(256) void reduce_attn_kernel(
    const float* __restrict__ bias) {
    const int idx = blockIdx.x * 256 + threadIdx.x;   // 128 blocks
    const int a = idx & (ATT_ - 1);
    float s = bias[a];
#pragma unroll
    for (int k = 0; k < KSPLIT; k++)
        s += g_attn_part[(size_t)k * B_ * ATT_ + idx];
    g_attn_h[idx] = s;
}

// ---------------------------------------------------------------------------
// Accurate fast tanh: 1 - 2/(exp(2x)+1).
// ---------------------------------------------------------------------------
__device__ __forceinline__ float fast_tanh(float x) {
    float e = __expf(2.0f * x);
    return 1.0f - __fdividef(2.0f, e + 1.0f);
}

// ---------------------------------------------------------------------------
// Kernel 2 (FUSED, software-pipelined): block = (chunk, b) owns 64 rows.
// 8 groups x 8 rows, double-buffered e-scores. Group body ordering:
//   1. issue ctx loads of rows 0-3 into registers (DRAM stream starts)
//   2. compute_e(g+1)  -- pc loads + MUFU overlap the in-flight ctx loads
//   3. FMA the preloaded half; load+FMA rows 4-7 inline
// One __syncthreads per group. Partials stay UNNORMALIZED (linearity);
// per-block e-sum -> g_bsum. mask read as promoted 4-byte bool.
// ---------------------------------------------------------------------------
__global__ __launch_bounds__(256) void fused_kernel(
    const float4* __restrict__ pc, const float4* __restrict__ context,
    const uint32_t* __restrict__ mask,
    const float4* __restrict__ w_alpha, const float* __restrict__ b_alpha) {
    const int b = blockIdx.y;
    const int chunk = blockIdx.x;
    const int s0 = chunk * SCHUNK;
    const int t = threadIdx.x;
    const int lane = t & 31, widx = t >> 5;

    __shared__ float esc[2][NGROUP];   // e of the 8 rows of each buffered group
    __shared__ float wsum[8];

    const float4* ah = (const float4*)g_attn_h + b * (ATT_ / 4);
    const float ba = b_alpha[0];
    float esum = 0.0f;                 // lane 0 of each warp: sum of its e's

    // warp widx computes row (s0 + g*8 + widx) of group g
    auto compute_e = [&](int g, int buf) {
        const int r = s0 + g * NGROUP + widx;
        const float4* prow = pc + ((size_t)b * S_ + r) * (ATT_ / 4);
        float sum = 0.0f;
#pragma unroll
        for (int i = 0; i < 4; i++) {
            int idx = lane + i * 32;
            float4 p = __ldcs(prow + idx);
            float4 a = ah[idx];
            float4 w = w_alpha[idx];
            sum += fast_tanh(p.x + a.x) * w.x;
            sum += fast_tanh(p.y + a.y) * w.y;
            sum += fast_tanh(p.z + a.z) * w.z;
            sum += fast_tanh(p.w + a.w) * w.w;
        }
#pragma unroll
        for (int off = 16; off; off >>= 1)
            sum += __shfl_xor_sync(0xFFFFFFFFu, sum, off);
        if (lane == 0) {
            float e = (mask[b * S_ + r] != 0u) ? 0.0f : expf(sum + ba);
            esc[buf][widx] = e;
            g_escores[b * S_ + r] = e;
            esum += e;
        }
    };

    compute_e(0, 0);
    __syncthreads();

    float4 acc = make_float4(0.f, 0.f, 0.f, 0.f);
#pragma unroll
    for (int g = 0; g < NGROUPS_PER_BLK; g++) {
        const float4* cbase =
            context + ((size_t)b * S_ + s0 + g * NGROUP) * (CTX_ / 4);

        // 1. issue first-half ctx loads (4 independent LDG.128 in flight)
        float4 v0 = __ldcs(cbase + 0 * (CTX_ / 4) + t);
        float4 v1 = __ldcs(cbase + 1 * (CTX_ / 4) + t);
        float4 v2 = __ldcs(cbase + 2 * (CTX_ / 4) + t);
        float4 v3 = __ldcs(cbase + 3 * (CTX_ / 4) + t);

        // 2. next group's e-scores overlap those loads
        if (g < NGROUPS_PER_BLK - 1)
            compute_e(g + 1, (g + 1) & 1);

        // 3. consume preloaded half
        const int buf = g & 1;
        float ww;
        ww = esc[buf][0];
        acc.x = fmaf(ww, v0.x, acc.x); acc.y = fmaf(ww, v0.y, acc.y);
        acc.z = fmaf(ww, v0.z, acc.z); acc.w = fmaf(ww, v0.w, acc.w);
        ww = esc[buf][1];
        acc.x = fmaf(ww, v1.x, acc.x); acc.y = fmaf(ww, v1.y, acc.y);
        acc.z = fmaf(ww, v1.z, acc.z); acc.w = fmaf(ww, v1.w, acc.w);
        ww = esc[buf][2];
        acc.x = fmaf(ww, v2.x, acc.x); acc.y = fmaf(ww, v2.y, acc.y);
        acc.z = fmaf(ww, v2.z, acc.z); acc.w = fmaf(ww, v2.w, acc.w);
        ww = esc[buf][3];
        acc.x = fmaf(ww, v3.x, acc.x); acc.y = fmaf(ww, v3.y, acc.y);
        acc.z = fmaf(ww, v3.z, acc.z); acc.w = fmaf(ww, v3.w, acc.w);

        // second half streamed inline
#pragma unroll
        for (int s = 4; s < NGROUP; s++) {
            float4 v = __ldcs(cbase + (size_t)s * (CTX_ / 4) + t);
            float w2 = esc[buf][s];
            acc.x = fmaf(w2, v.x, acc.x);
            acc.y = fmaf(w2, v.y, acc.y);
            acc.z = fmaf(w2, v.z, acc.z);
            acc.w = fmaf(w2, v.w, acc.w);
        }
        __syncthreads();
    }
    ((float4*)g_partial)[((size_t)chunk * B_ + b) * (CTX_ / 4) + t] = acc;

    if (lane == 0) wsum[widx] = esum;
    __syncthreads();
    if (t == 0) {
        float s = 0.0f;
#pragma unroll
        for (int i = 0; i < 8; i++) s += wsum[i];
        g_bsum[b * NCHUNK + chunk] = s;
    }
}

// ---------------------------------------------------------------------------
// Kernel 3 (finalize): grid (6, B) x 256  (R13 shape — measured best).
//   total = fixed-order shuffle tree over the 32 bsums of row b.
//   parts 0-1: wctx reduce, 128 float4-cols per part, TWO threads per column
//              (fixed 16-chunk halves; deterministic low+high combine).
//   parts 2-5: attn_out = e * inv over a 512-element slice.
// ---------------------------------------------------------------------------
__global__ __launch_bounds__(256) void finalize_kernel(
    float* __restrict__ wctx_out, float* __restrict__ attn_out) {
    const int b = blockIdx.y;
    const int part = blockIdx.x;
    const int t = threadIdx.x;

    __shared__ float total_sh;
    if (t < 32) {
        float v = g_bsum[b * NCHUNK + t];
#pragma unroll
        for (int off = 16; off; off >>= 1)
            v += __shfl_xor_sync(0xFFFFFFFFu, v, off);
        if (t == 0) total_sh = v;
    }
    __syncthreads();
    const float total = total_sh;
    const float inv = (total > 0.0f) ? __fdividef(1.0f, total) : 0.0f;

    if (part < 2) {
        __shared__ float4 hi_sh[128];
        const int col = t >> 1;                // 0..127 within part
        const int half = t & 1;                // which 16-chunk half
        const int c4 = part * 128 + col;       // global float4 column 0..255
        const float4* pp = (const float4*)g_partial;
        float4 acc = make_float4(0.f, 0.f, 0.f, 0.f);
#pragma unroll
        for (int i = 0; i < 16; i++) {
            int c = half * 16 + i;
            float4 v = pp[((size_t)c * B_ + b) * (CTX_ / 4) + c4];
            acc.x += v.x; acc.y += v.y; acc.z += v.z; acc.w += v.w;
        }
        if (half == 1) hi_sh[col] = acc;
        __syncthreads();
        if (half == 0) {
            float4 hv = hi_sh[col];            // fixed order: low + high
            acc.x = (acc.x + hv.x) * inv;
            acc.y = (acc.y + hv.y) * inv;
            acc.z = (acc.z + hv.z) * inv;
            acc.w = (acc.w + hv.w) * inv;
            ((float4*)wctx_out)[b * (CTX_ / 4) + c4] = acc;
        }
    } else {
        const int p = part - 2;                // 0..3, 512 elems each
        const float* row = g_escores + b * S_;
        float* out = attn_out + b * S_;
#pragma unroll
        for (int i = 0; i < 2; i++) {
            int s = p * 512 + i * 256 + t;
            out[s] = (total > 0.0f) ? row[s] * inv : (1.0f / S_);
        }
    }
}

// ---------------------------------------------------------------------------
extern "C" void kernel_launch(void* const* d_in, const int* in_sizes, int n_in,
                              void* d_out, int out_size) {
    const float*    h    = (const float*)d_in[0];
    const float*    pc   = (const float*)d_in[1];
    const float*    ctx  = (const float*)d_in[2];
    const uint32_t* mask = (const uint32_t*)d_in[3];
    const float*    W    = (const float*)d_in[4];
    const float*    bh   = (const float*)d_in[5];
    const float*    wa   = (const float*)d_in[6];
    const float*    ba   = (const float*)d_in[7];

    float* out      = (float*)d_out;
    float* wctx_out = out;               // [B, CTX]
    float* attn_out = out + B_ * CTX_;   // [B, S]

    attn_h_kernel<<<dim3(ATT_ / BN, KSPLIT), 256>>>(h, W);
    reduce_attn_kernel<<<(B_ * ATT_) / 256, 256>>>(bh);
    fused_kernel<<<dim3(NCHUNK, B_), 256>>>((const float4*)pc,
                                            (const float4*)ctx, mask,
                                            (const float4*)wa, ba);
    finalize_kernel<<<dim3(6, B_), 256>>>(wctx_out, attn_out);
}

// round 16
// speedup vs baseline: 1.1039x; 1.1039x over previous
#include <cuda_runtime.h>
#include <cstdint>

#define B_   64
#define S_   2048
#define RNN_ 1024
#define ATT_ 512
#define CTX_ 1024

#define NCHUNK 32
#define SCHUNK (S_ / NCHUNK)   // 64 rows per fused block
#define NGROUP 8               // pipeline groups of 8 rows
#define NGROUPS_PER_BLK (SCHUNK / NGROUP)  // 8

#define KSPLIT 32
#define KCHUNK (RNN_ / KSPLIT) // 32 = exactly one BK tile per block

// Scratch (no allocations allowed in kernel_launch)
__device__ float g_attn_part[KSPLIT * B_ * ATT_];
__device__ float g_attn_h[B_ * ATT_];
__device__ float g_escores[B_ * S_];        // UNNORMALIZED exp(score), masked -> 0
__device__ float g_bsum[B_ * NCHUNK];       // per-block e-sums (32 per batch row)
__device__ float g_partial[NCHUNK * B_ * CTX_];   // UNNORMALIZED e-weighted partials

// PDL primitives: wait-for-predecessor (no-op when launched without PDL) and
// allow-dependents-to-launch.
__device__ __forceinline__ void pdl_wait() {
    asm volatile("griddepcontrol.wait;" ::: "memory");
}
__device__ __forceinline__ void pdl_launch_dependents() {
    asm volatile("griddepcontrol.launch_dependents;" ::: "memory");
}

// ---------------------------------------------------------------------------
// Kernel 1: split-K GEMM partials.  grid = (8 n-tiles, 32 k-chunks) = 256
// blocks, ONE BK=32 k-tile each (no loop-carried smem dependency).
// ---------------------------------------------------------------------------
#define BM 64
#define BN 64
#define BK 32
__global__ __launch_bounds__(256) void attn_h_kernel(
    const float* __restrict__ h, const float* __restrict__ W) {
    pdl_launch_dependents();
    __shared__ float As[BM][BK + 1];
    __shared__ float Bs[BN][BK + 1];
    const int a0 = blockIdx.x * BN;
    const int k0 = blockIdx.y * KCHUNK;
    const int tx = threadIdx.x & 15;
    const int ty = threadIdx.x >> 4;
    float acc[4][4] = {};

    for (int i = threadIdx.x; i < BM * BK; i += 256) {
        int r = i >> 5, c = i & 31;
        As[r][c] = h[r * RNN_ + k0 + c];
    }
    for (int i = threadIdx.x; i < BN * BK; i += 256) {
        int r = i >> 5, c = i & 31;
        Bs[r][c] = W[(a0 + r) * RNN_ + k0 + c];
    }
    __syncthreads();
#pragma unroll
    for (int k = 0; k < BK; k++) {
        float av[4], bv[4];
#pragma unroll
        for (int i = 0; i < 4; i++) av[i] = As[ty * 4 + i][k];
#pragma unroll
        for (int j = 0; j < 4; j++) bv[j] = Bs[tx * 4 + j][k];
#pragma unroll
        for (int i = 0; i < 4; i++)
#pragma unroll
            for (int j = 0; j < 4; j++)
                acc[i][j] = fmaf(av[i], bv[j], acc[i][j]);
    }
    float* part = g_attn_part + (size_t)blockIdx.y * B_ * ATT_;
#pragma unroll
    for (int i = 0; i < 4; i++)
#pragma unroll
        for (int j = 0; j < 4; j++)
            part[(ty * 4 + i) * ATT_ + a0 + tx * 4 + j] = acc[i][j];
}

// ---------------------------------------------------------------------------
// Kernel 1b: reduce split-K partials + bias -> attn_h (fixed order).
// ---------------------------------------------------------------------------
__global__ __launch_bounds__(256) void reduce_attn_kernel(
    const float* __restrict__ bias) {
    pdl_wait();                          // g_attn_part must be complete
    pdl_launch_dependents();
    const int idx = blockIdx.x * 256 + threadIdx.x;   // 128 blocks
    const int a = idx & (ATT_ - 1);
    float s = bias[a];
#pragma unroll
    for (int k = 0; k < KSPLIT; k++)
        s += g_attn_part[(size_t)k * B_ * ATT_ + idx];
    g_attn_h[idx] = s;
}

// ---------------------------------------------------------------------------
// Accurate fast tanh: 1 - 2/(exp(2x)+1).
// ---------------------------------------------------------------------------
__device__ __forceinline__ float fast_tanh(float x) {
    float e = __expf(2.0f * x);
    return 1.0f - __fdividef(2.0f, e + 1.0f);
}

// ---------------------------------------------------------------------------
// Kernel 2 (FUSED, software-pipelined — R13 body, frozen): block = (chunk, b)
// owns 64 rows. 8 groups x 8 rows, double-buffered e-scores:
//   iteration g: warps compute e of group g+1 (pc stream + MUFU) while the
//   block streams context of group g (DRAM) weighted by esc[g&1].
// One __syncthreads per group. Partials stay UNNORMALIZED (linearity);
// per-block e-sum -> g_bsum. mask read as promoted 4-byte bool.
// ---------------------------------------------------------------------------
__global__ __launch_bounds__(256) void fused_kernel(
    const float4* __restrict__ pc, const float4* __restrict__ context,
    const uint32_t* __restrict__ mask,
    const float4* __restrict__ w_alpha, const float* __restrict__ b_alpha) {
    pdl_wait();                          // g_attn_h must be complete
    pdl_launch_dependents();
    const int b = blockIdx.y;
    const int chunk = blockIdx.x;
    const int s0 = chunk * SCHUNK;
    const int t = threadIdx.x;
    const int lane = t & 31, widx = t >> 5;

    __shared__ float esc[2][NGROUP];   // e of the 8 rows of each buffered group
    __shared__ float wsum[8];

    const float4* ah = (const float4*)g_attn_h + b * (ATT_ / 4);
    const float ba = b_alpha[0];
    float esum = 0.0f;                 // lane 0 of each warp: sum of its e's

    // warp widx computes row (s0 + g*8 + widx) of group g
    auto compute_e = [&](int g, int buf) {
        const int r = s0 + g * NGROUP + widx;
        const float4* prow = pc + ((size_t)b * S_ + r) * (ATT_ / 4);
        float sum = 0.0f;
#pragma unroll
        for (int i = 0; i < 4; i++) {
            int idx = lane + i * 32;
            float4 p = __ldcs(prow + idx);
            float4 a = ah[idx];
            float4 w = w_alpha[idx];
            sum += fast_tanh(p.x + a.x) * w.x;
            sum += fast_tanh(p.y + a.y) * w.y;
            sum += fast_tanh(p.z + a.z) * w.z;
            sum += fast_tanh(p.w + a.w) * w.w;
        }
#pragma unroll
        for (int off = 16; off; off >>= 1)
            sum += __shfl_xor_sync(0xFFFFFFFFu, sum, off);
        if (lane == 0) {
            float e = (mask[b * S_ + r] != 0u) ? 0.0f : expf(sum + ba);
            esc[buf][widx] = e;
            g_escores[b * S_ + r] = e;
            esum += e;
        }
    };

    compute_e(0, 0);
    __syncthreads();

    float4 acc = make_float4(0.f, 0.f, 0.f, 0.f);
#pragma unroll
    for (int g = 0; g < NGROUPS_PER_BLK; g++) {
        if (g < NGROUPS_PER_BLK - 1)
            compute_e(g + 1, (g + 1) & 1);     // next group's e (pc + MUFU)
        const float4* cbase =
            context + ((size_t)b * S_ + s0 + g * NGROUP) * (CTX_ / 4);
#pragma unroll
        for (int s = 0; s < NGROUP; s++) {     // this group's ctx (DRAM)
            float4 v = __ldcs(cbase + (size_t)s * (CTX_ / 4) + t);
            float ww = esc[g & 1][s];
            acc.x = fmaf(ww, v.x, acc.x);
            acc.y = fmaf(ww, v.y, acc.y);
            acc.z = fmaf(ww, v.z, acc.z);
            acc.w = fmaf(ww, v.w, acc.w);
        }
        __syncthreads();
    }
    ((float4*)g_partial)[((size_t)chunk * B_ + b) * (CTX_ / 4) + t] = acc;

    if (lane == 0) wsum[widx] = esum;
    __syncthreads();
    if (t == 0) {
        float s = 0.0f;
#pragma unroll
        for (int i = 0; i < 8; i++) s += wsum[i];
        g_bsum[b * NCHUNK + chunk] = s;
    }
}

// ---------------------------------------------------------------------------
// Kernel 3 (finalize): grid (6, B) x 256  (R13 shape — measured best).
//   total = fixed-order shuffle tree over the 32 bsums of row b.
//   parts 0-1: wctx reduce, 128 float4-cols per part, TWO threads per column
//              (fixed 16-chunk halves; deterministic low+high combine).
//   parts 2-5: attn_out = e * inv over a 512-element slice.
// ---------------------------------------------------------------------------
__global__ __launch_bounds__(256) void finalize_kernel(
    float* __restrict__ wctx_out, float* __restrict__ attn_out) {
    pdl_wait();                          // g_partial/g_bsum/g_escores complete
    const int b = blockIdx.y;
    const int part = blockIdx.x;
    const int t = threadIdx.x;

    __shared__ float total_sh;
    if (t < 32) {
        float v = g_bsum[b * NCHUNK + t];
#pragma unroll
        for (int off = 16; off; off >>= 1)
            v += __shfl_xor_sync(0xFFFFFFFFu, v, off);
        if (t == 0) total_sh = v;
    }
    __syncthreads();
    const float total = total_sh;
    const float inv = (total > 0.0f) ? __fdividef(1.0f, total) : 0.0f;

    if (part < 2) {
        __shared__ float4 hi_sh[128];
        const int col = t >> 1;                // 0..127 within part
        const int half = t & 1;                // which 16-chunk half
        const int c4 = part * 128 + col;       // global float4 column 0..255
        const float4* pp = (const float4*)g_partial;
        float4 acc = make_float4(0.f, 0.f, 0.f, 0.f);
#pragma unroll
        for (int i = 0; i < 16; i++) {
            int c = half * 16 + i;
            float4 v = pp[((size_t)c * B_ + b) * (CTX_ / 4) + c4];
            acc.x += v.x; acc.y += v.y; acc.z += v.z; acc.w += v.w;
        }
        if (half == 1) hi_sh[col] = acc;
        __syncthreads();
        if (half == 0) {
            float4 hv = hi_sh[col];            // fixed order: low + high
            acc.x = (acc.x + hv.x) * inv;
            acc.y = (acc.y + hv.y) * inv;
            acc.z = (acc.z + hv.z) * inv;
            acc.w = (acc.w + hv.w) * inv;
            ((float4*)wctx_out)[b * (CTX_ / 4) + c4] = acc;
        }
    } else {
        const int p = part - 2;                // 0..3, 512 elems each
        const float* row = g_escores + b * S_;
        float* out = attn_out + b * S_;
#pragma unroll
        for (int i = 0; i < 2; i++) {
            int s = p * 512 + i * 256 + t;
            out[s] = (total > 0.0f) ? row[s] * inv : (1.0f / S_);
        }
    }
}

// ---------------------------------------------------------------------------
// PDL-aware launcher: attribute launch with plain fallback (worst case = R13).
// ---------------------------------------------------------------------------
static inline void launch_k(const void* func, dim3 grid, dim3 block,
                            void** args, bool pdl) {
    cudaLaunchConfig_t cfg = {};
    cfg.gridDim = grid;
    cfg.blockDim = block;
    cfg.dynamicSmemBytes = 0;
    cfg.stream = 0;
    cudaLaunchAttribute attr[1];
    attr[0].id = cudaLaunchAttributeProgrammaticStreamSerialization;
    attr[0].val.programmaticStreamSerializationAllowed = 1;
    cfg.attrs = attr;
    cfg.numAttrs = pdl ? 1 : 0;
    if (cudaLaunchKernelExC(&cfg, func, args) != cudaSuccess) {
        cudaLaunchKernel(func, grid, block, args, 0, 0);
    }
}

// ---------------------------------------------------------------------------
extern "C" void kernel_launch(void* const* d_in, const int* in_sizes, int n_in,
                              void* d_out, int out_size) {
    const float*    h    = (const float*)d_in[0];
    const float*    pc   = (const float*)d_in[1];
    const float*    ctx  = (const float*)d_in[2];
    const uint32_t* mask = (const uint32_t*)d_in[3];
    const float*    W    = (const float*)d_in[4];
    const float*    bh   = (const float*)d_in[5];
    const float*    wa   = (const float*)d_in[6];
    const float*    ba   = (const float*)d_in[7];

    float* out      = (float*)d_out;
    float* wctx_out = out;               // [B, CTX]
    float* attn_out = out + B_ * CTX_;   // [B, S]

    {   // attn_h: first kernel, no predecessor
        void* args[] = {(void*)&h, (void*)&W};
        launch_k((const void*)attn_h_kernel,
                 dim3(ATT_ / BN, KSPLIT), dim3(256), args, false);
    }
    {   // reduce_attn: PDL after attn_h
        void* args[] = {(void*)&bh};
        launch_k((const void*)reduce_attn_kernel,
                 dim3((B_ * ATT_) / 256), dim3(256), args, true);
    }
    {   // fused: PDL after reduce_attn
        const float4* pc4 = (const float4*)pc;
        const float4* ctx4 = (const float4*)ctx;
        const float4* wa4 = (const float4*)wa;
        void* args[] = {(void*)&pc4, (void*)&ctx4, (void*)&mask,
                        (void*)&wa4, (void*)&ba};
        launch_k((const void*)fused_kernel,
                 dim3(NCHUNK, B_), dim3(256), args, true);
    }
    {   // finalize: PDL after fused
        void* args[] = {(void*)&wctx_out, (void*)&attn_out};
        launch_k((const void*)finalize_kernel,
                 dim3(6, B_), dim3(256), args, true);
    }
}